// round 15
// baseline (speedup 1.0000x reference)
#include <cuda_runtime.h>
#include <cuda_fp16.h>
#include <math_constants.h>
#include <cstdint>

// Problem constants (fixed by setup_inputs)
#define BB 2
#define SS 2048
#define HH 16
#define DKK 64
#define DD 1024
#define MM (BB*SS)   // 4096

// Scratch (allocation-free rule: __device__ globals)
__device__ __half g_xh[(size_t)MM * DD];         // fp16 x
__device__ __half g_wh[4 * (size_t)DD * DD];     // fp16 Wq,Wk,Wv,Wo (contiguous)
__device__ __half g_qh[(size_t)MM * DD];         // Q (pre-scaled by log2e/8, RoPE'd)
__device__ __half g_kh[(size_t)MM * DD];
__device__ __half g_vh[(size_t)MM * DD];
__device__ __half g_ah[(size_t)MM * DD];         // attention output
__device__ float2 g_rope[(size_t)MM * 32];       // (cos, sin) per (row, freq)

__device__ __forceinline__ void mma_f16(
    float& d0, float& d1, float& d2, float& d3,
    uint32_t a0, uint32_t a1, uint32_t a2, uint32_t a3,
    uint32_t b0, uint32_t b1)
{
    asm volatile(
        "mma.sync.aligned.m16n8k16.row.col.f32.f16.f16.f32 "
        "{%0,%1,%2,%3}, {%4,%5,%6,%7}, {%8,%9}, {%0,%1,%2,%3};\n"
        : "+f"(d0), "+f"(d1), "+f"(d2), "+f"(d3)
        : "r"(a0), "r"(a1), "r"(a2), "r"(a3), "r"(b0), "r"(b1));
}

#define LDSM_X4(r0,r1,r2,r3,addr) \
    asm volatile("ldmatrix.sync.aligned.m8n8.x4.shared.b16 {%0,%1,%2,%3}, [%4];" \
        : "=r"(r0), "=r"(r1), "=r"(r2), "=r"(r3) : "r"(addr))

#define LDSM_X4_T(r0,r1,r2,r3,addr) \
    asm volatile("ldmatrix.sync.aligned.m8n8.x4.trans.shared.b16 {%0,%1,%2,%3}, [%4];" \
        : "=r"(r0), "=r"(r1), "=r"(r2), "=r"(r3) : "r"(addr))

__device__ __forceinline__ void cp_async16(uint32_t dst, const void* src) {
    asm volatile("cp.async.cg.shared.global [%0], [%1], 16;\n" :: "r"(dst), "l"(src));
}

__device__ __forceinline__ uint32_t pack_h2(float lo, float hi) {
    __half2 h = __float22half2_rn(make_float2(lo, hi));
    return *(uint32_t*)&h;
}

__device__ __forceinline__ float ex2f(float x) {
    float y;
    asm("ex2.approx.f32 %0, %1;" : "=f"(y) : "f"(x));
    return y;
}

// pack (a,b) to half2 then 2^x elementwise with ONE MUFU op
__device__ __forceinline__ uint32_t h2ex2(float a, float b) {
    __half2 h = __float22half2_rn(make_float2(a, b));
    uint32_t u = *(uint32_t*)&h;
    asm("ex2.approx.f16x2 %0, %0;" : "+r"(u));
    return u;
}

// ---------------------------------------------------------------------------
// Fused prepass: fp16 conversion of x + 4 weights, AND RoPE table build.
// ---------------------------------------------------------------------------
#define NX8 (MM * DD / 8)        // 524288
#define NW8 (DD * DD / 8)        // 131072
#define NCVT (NX8 + 4 * NW8)     // 1048576
#define NPRE (NCVT + MM * 32)    // + rope units = 1179648

__global__ __launch_bounds__(256) void prepass_kernel(
    const float4* __restrict__ x,
    const float4* __restrict__ wq, const float4* __restrict__ wk,
    const float4* __restrict__ wv, const float4* __restrict__ wo,
    __half* __restrict__ xh, __half* __restrict__ wh,
    const int* __restrict__ pos, float2* __restrict__ rope)
{
    int i = blockIdx.x * 256 + threadIdx.x;
    if (i < NCVT) {
        const float4* src;
        __half* dst;
        int off;
        if (i < NX8) { src = x; dst = xh; off = i; }
        else {
            int j = i - NX8;
            int w = j / NW8;
            off = j - w * NW8;
            src = (w == 0) ? wq : (w == 1) ? wk : (w == 2) ? wv : wo;
            dst = wh + (size_t)w * (DD * DD);
        }
        float4 f0 = src[2 * off];
        float4 f1 = src[2 * off + 1];
        uint32_t h[4];
        h[0] = pack_h2(f0.x, f0.y);
        h[1] = pack_h2(f0.z, f0.w);
        h[2] = pack_h2(f1.x, f1.y);
        h[3] = pack_h2(f1.z, f1.w);
        *(uint4*)&dst[(size_t)off * 8] = make_uint4(h[0], h[1], h[2], h[3]);
    } else {
        int j = i - NCVT;                     // 0 .. MM*32-1
        int m = j >> 5, f = j & 31;
        const float KF = 0.14391157f;         // ln(10000)/64
        float invf = expf(-2.0f * (float)f * KF);
        float a = (float)pos[m] * invf;
        float sn, cs;
        sincosf(a, &sn, &cs);
        rope[j] = make_float2(cs, sn);
    }
}

// ---------------------------------------------------------------------------
// fp16 mma GEMM: C[M,N] = A[M,K] @ W[N,K]^T + bias (f32 accumulate).
// R12/R14 champion config: CTA tile 128x128, 8 warps of 64x32 (2Mx4N),
// 2 CTAs/SM. 4-stage cp.async ring, pair-loaded chunks, 1 sync / 2 chunks.
// ---------------------------------------------------------------------------
#define GROWB 80                    // bytes per smem row (40 halves)
#define G_A_BYTES (128 * GROWB)     // 10240
#define GSTG_B (2 * G_A_BYTES)      // 20480 per stage (A+B)
#define GNSTG 4
#define GEMM_SMEM (GNSTG * GSTG_B)  // 81920
#define GNC (DD / 32)               // 32 chunks (even)

__global__ __launch_bounds__(256, 2) void gemm_h_kernel(
    const __half* __restrict__ A, const __half* __restrict__ W,
    const float* __restrict__ bQ, const float* __restrict__ bK,
    const float* __restrict__ bV,
    const float2* __restrict__ rope,
    __half* __restrict__ oQ, __half* __restrict__ oK, __half* __restrict__ oV,
    float* __restrict__ outF, int mode)
{
    extern __shared__ char smc[];
    const uint32_t smem_u = (uint32_t)__cvta_generic_to_shared(smc);

    const int tid = threadIdx.x;
    const int lane = tid & 31;
    const int wid = tid >> 5;                 // 0..7
    const int g = lane >> 2;
    const int t = lane & 3;
    const int wm0 = (wid >> 2) * 64;          // 2 M groups
    const int wn0 = (wid & 3) * 32;           // 4 N groups
    const int m0 = blockIdx.y * 128;
    const int n0 = blockIdx.x * 128;

    // loader: chunk = 128 rows x 4 segs(16B) per matrix; 2 A + 2 B per thread
    const int seg = tid & 3;
    const int rbase = tid >> 2;               // 0..63; rows rbase + 64j
    const __half* aoff = A + (size_t)(m0 + rbase) * DD + seg * 8;
    const __half* boff = W + (size_t)(n0 + rbase) * DD + seg * 8;
    const uint32_t sdst = (uint32_t)(rbase * GROWB + seg * 16);

    float d[4][4][4];
    #pragma unroll
    for (int mt = 0; mt < 4; ++mt)
        #pragma unroll
        for (int nt = 0; nt < 4; ++nt)
            #pragma unroll
            for (int e = 0; e < 4; ++e) d[mt][nt][e] = 0.f;

    // prologue: chunks 0,1 as ONE group
    #pragma unroll
    for (int p = 0; p < 2; ++p) {
        uint32_t sb = smem_u + p * GSTG_B + sdst;
        #pragma unroll
        for (int j = 0; j < 2; ++j) {
            cp_async16(sb + j * (64 * GROWB), aoff + (size_t)j * 64 * DD + p * 32);
            cp_async16(sb + G_A_BYTES + j * (64 * GROWB), boff + (size_t)j * 64 * DD + p * 32);
        }
    }
    asm volatile("cp.async.commit_group;" ::: "memory");

    const uint32_t a_lrow = (uint32_t)((lane & 15) * GROWB + ((lane >> 4) << 4));
    const uint32_t b_lrow = (uint32_t)(((lane & 7) + ((lane >> 4) << 3)) * GROWB
                                       + (((lane >> 3) & 1) << 4));

    for (int kc = 0; kc < GNC; ++kc) {
        if ((kc & 1) == 0) {
            asm volatile("cp.async.wait_group 0;" ::: "memory");
            __syncthreads();
            if (kc + 2 < GNC) {
                #pragma unroll
                for (int p = 0; p < 2; ++p) {
                    const int c = kc + 2 + p;
                    uint32_t sb = smem_u + (c & 3) * GSTG_B + sdst;
                    const int ko = c * 32;
                    #pragma unroll
                    for (int j = 0; j < 2; ++j) {
                        cp_async16(sb + j * (64 * GROWB), aoff + (size_t)j * 64 * DD + ko);
                        cp_async16(sb + G_A_BYTES + j * (64 * GROWB), boff + (size_t)j * 64 * DD + ko);
                    }
                }
                asm volatile("cp.async.commit_group;" ::: "memory");
            }
        }

        const uint32_t Sa = smem_u + (kc & 3) * GSTG_B;
        const uint32_t Sb = Sa + G_A_BYTES;

        #pragma unroll
        for (int ks = 0; ks < 2; ++ks) {
            uint32_t a[4][4], b[2][4];
            #pragma unroll
            for (int mt = 0; mt < 4; ++mt)
                LDSM_X4(a[mt][0], a[mt][1], a[mt][2], a[mt][3],
                        Sa + (wm0 + mt * 16) * GROWB + a_lrow + ks * 32);
            #pragma unroll
            for (int np = 0; np < 2; ++np)
                LDSM_X4(b[np][0], b[np][1], b[np][2], b[np][3],
                        Sb + (wn0 + np * 16) * GROWB + b_lrow + ks * 32);
            #pragma unroll
            for (int mt = 0; mt < 4; ++mt)
                #pragma unroll
                for (int np = 0; np < 2; ++np) {
                    mma_f16(d[mt][2*np][0], d[mt][2*np][1], d[mt][2*np][2], d[mt][2*np][3],
                            a[mt][0], a[mt][1], a[mt][2], a[mt][3], b[np][0], b[np][1]);
                    mma_f16(d[mt][2*np+1][0], d[mt][2*np+1][1], d[mt][2*np+1][2], d[mt][2*np+1][3],
                            a[mt][0], a[mt][1], a[mt][2], a[mt][3], b[np][2], b[np][3]);
                }
        }
    }

    // ---- epilogue (warp tile 64x32) ----
    #pragma unroll
    for (int mt = 0; mt < 4; ++mt) {
        int r0 = m0 + wm0 + mt * 16 + g;
        int r1 = r0 + 8;
        const float2* rp0 = rope + (size_t)r0 * 32;
        const float2* rp1 = rope + (size_t)r1 * 32;
        #pragma unroll
        for (int nt = 0; nt < 4; ++nt) {
            int c = n0 + wn0 + nt * 8 + 2 * t;
            if (mode == 0) {
                float bv0 = __ldg(bQ + c), bv1 = __ldg(bQ + c + 1);
                *(float2*)&outF[(size_t)r0 * DD + c] =
                    make_float2(d[mt][nt][0] + bv0, d[mt][nt][1] + bv1);
                *(float2*)&outF[(size_t)r1 * DD + c] =
                    make_float2(d[mt][nt][2] + bv0, d[mt][nt][3] + bv1);
            } else {
                const int which = c >> 10;        // 0=Q 1=K 2=V
                const int cc = c & 1023;
                const int h = cc >> 6, cl = cc & 63;
                const float* bp = (which == 0) ? bQ : (which == 1) ? bK : bV;
                __half* outp = (which == 0) ? oQ : (which == 1) ? oK : oV;
                float bv0 = __ldg(bp + cc), bv1 = __ldg(bp + cc + 1);
                float v00 = d[mt][nt][0] + bv0, v01 = d[mt][nt][1] + bv1;
                float v10 = d[mt][nt][2] + bv0, v11 = d[mt][nt][3] + bv1;
                if (which < 2) {                  // RoPE on Q,K
                    float2 cs0 = rp0[cl >> 1], cs1 = rp1[cl >> 1];
                    float e, od;
                    e  = v00 * cs0.x - v01 * cs0.y;
                    od = v00 * cs0.y + v01 * cs0.x;  v00 = e; v01 = od;
                    e  = v10 * cs1.x - v11 * cs1.y;
                    od = v10 * cs1.y + v11 * cs1.x;  v10 = e; v11 = od;
                }
                // Q pre-scale: (1/sqrt(dk)) * log2(e) -> flash softmax in log2 domain
                float sc = (which == 0) ? 0.18033688f : 1.0f;
                int b0i = r0 >> 11, s0 = r0 & (SS - 1);
                int b1i = r1 >> 11, s1 = r1 & (SS - 1);
                size_t o0 = (((size_t)(b0i * HH + h) * SS + s0) * DKK) + cl;
                size_t o1 = (((size_t)(b1i * HH + h) * SS + s1) * DKK) + cl;
                *(__half2*)&outp[o0] = __float22half2_rn(make_float2(v00 * sc, v01 * sc));
                *(__half2*)&outp[o1] = __float22half2_rn(make_float2(v10 * sc, v11 * sc));
            }
        }
    }
}

// ---------------------------------------------------------------------------
// fp16 tensor-core flash attention (log2-domain softmax, causal).
// vs R14: (1) ones-mma removed — row sums from pa via HADD2 + fp32 accum;
// (2) diagonal block skipping — QK 16-col blocks and PV 16-row ks blocks
// fully above a warp's rows are skipped (warp-uniform branches).
// Br=128 (8 warps x 16 rows), Bc=64, 4-stage pair-loaded KV ring.
// ---------------------------------------------------------------------------
#define FROWB 144                       // bytes per smem row (72 halves)
#define FTILE_B (64 * FROWB)            // 9216 B per tensor per stage
#define FSTG_B (2 * FTILE_B)            // 18432 B per stage (K+V)
#define FNSTG 4
#define FLASH_SMEM (FNSTG * FSTG_B)     // 73728 B

__global__ __launch_bounds__(256, 2) void flash_h_kernel(
    const __half* __restrict__ Qg, const __half* __restrict__ Kg,
    const __half* __restrict__ Vg, __half* __restrict__ Og)
{
    extern __shared__ char smc[];
    __half* smh = (__half*)smc;
    const uint32_t smem_u = (uint32_t)__cvta_generic_to_shared(smc);

    const int qi = (int)(gridDim.x - 1) - (int)blockIdx.x;  // big tiles first
    const int bh = blockIdx.y;
    const int q0 = qi * 128;
    const __half* Qb = Qg + (size_t)bh * SS * DKK;
    const __half* Kb = Kg + (size_t)bh * SS * DKK;
    const __half* Vb = Vg + (size_t)bh * SS * DKK;

    const int tid = threadIdx.x;
    const int lane = tid & 31;
    const int wid = tid >> 5;
    const int g = lane >> 2;
    const int t = lane & 3;
    const int wr = wid * 16;          // warp row base (0..112)

    // ---- stage Q tile (128 x 64 halves, row stride 72) into stage-0 area ----
    #pragma unroll
    for (int j = 0; j < 4; ++j) {
        int u = tid + j * 256;        // 0..1023
        int row = u >> 3;
        int sg = u & 7;
        uint4 v = *(const uint4*)&Qb[(size_t)(q0 + row) * DKK + sg * 8];
        *(uint4*)&smh[row * 72 + sg * 8] = v;
    }
    __syncthreads();

    const uint32_t a_lrow = (uint32_t)((lane & 15) * FROWB + ((lane >> 4) << 4));
    uint32_t qf[4][4];
    #pragma unroll
    for (int ks = 0; ks < 4; ++ks)
        LDSM_X4(qf[ks][0], qf[ks][1], qf[ks][2], qf[ks][3],
                smem_u + wr * FROWB + a_lrow + ks * 32);
    __syncthreads();   // Q reads done before KV tile 0 overwrites stage 0

    // KV loader: 64 rows x 8 segs per tensor; 2 K + 2 V segs per thread
    const int fr = tid >> 3;
    const int fsg = tid & 7;
    const __half* ksrc = Kb + (size_t)fr * DKK + fsg * 8;
    const __half* vsrc = Vb + (size_t)fr * DKK + fsg * 8;
    const uint32_t kdst = smem_u + (uint32_t)(fr * FROWB + fsg * 16);
    const uint32_t vdst = kdst + FTILE_B;

    const int rmax = q0 + wr + 15;
    const int ktend = 2 * qi + 2;     // even

    // prologue: KV tiles 0,1 as ONE group
    #pragma unroll
    for (int p = 0; p < 2; ++p) {
        uint32_t so = (uint32_t)(p * FSTG_B);
        const size_t go = (size_t)p * 64 * DKK;
        #pragma unroll
        for (int j = 0; j < 2; ++j) {
            cp_async16(kdst + so + j * (32 * FROWB), ksrc + go + (size_t)j * 32 * DKK);
            cp_async16(vdst + so + j * (32 * FROWB), vsrc + go + (size_t)j * 32 * DKK);
        }
    }
    asm volatile("cp.async.commit_group;" ::: "memory");

    const uint32_t b_lrow = (uint32_t)(((lane & 7) + ((lane >> 4) << 3)) * FROWB
                                       + (((lane >> 3) & 1) << 4));
    const uint32_t v_lrow = (uint32_t)(((lane & 7) + (((lane >> 3) & 1) << 3)) * FROWB
                                       + ((lane >> 4) << 4));

    float o[8][4];
    #pragma unroll
    for (int nt = 0; nt < 8; ++nt)
        #pragma unroll
        for (int e = 0; e < 4; ++e) o[nt][e] = 0.f;
    float l0 = 0.f, l1 = 0.f;             // fp32 row-sum accumulators
    float m0 = -CUDART_INF_F, m1 = -CUDART_INF_F;

    for (int kt = 0; kt < ktend; ++kt) {
        const int k0 = kt * 64;

        if ((kt & 1) == 0) {
            asm volatile("cp.async.wait_group 0;" ::: "memory");
            __syncthreads();
            if (kt + 2 < ktend) {
                #pragma unroll
                for (int p = 0; p < 2; ++p) {
                    const int tt = kt + 2 + p;
                    uint32_t so = (uint32_t)((tt & 3) * FSTG_B);
                    const size_t go = (size_t)tt * 64 * DKK;
                    #pragma unroll
                    for (int j = 0; j < 2; ++j) {
                        cp_async16(kdst + so + j * (32 * FROWB), ksrc + go + (size_t)j * 32 * DKK);
                        cp_async16(vdst + so + j * (32 * FROWB), vsrc + go + (size_t)j * 32 * DKK);
                    }
                }
                asm volatile("cp.async.commit_group;" ::: "memory");
            }
        }

        if (k0 <= rmax) {
            const int kmax_rel = rmax - k0;     // warp-uniform, >= 0
            const uint32_t Ks = smem_u + (kt & 3) * FSTG_B;
            const uint32_t Vs = Ks + FTILE_B;

            // ---- S = Q @ K^T (log2-domain scores); skip fully-masked blocks ----
            float s[8][4];
            #pragma unroll
            for (int nt = 0; nt < 8; ++nt)
                #pragma unroll
                for (int e = 0; e < 4; ++e) s[nt][e] = 0.f;

            #pragma unroll
            for (int ks = 0; ks < 4; ++ks) {
                uint32_t b[4][4];
                #pragma unroll
                for (int np = 0; np < 4; ++np)
                    if (np * 16 <= kmax_rel)
                        LDSM_X4(b[np][0], b[np][1], b[np][2], b[np][3],
                                Ks + (np * 16) * FROWB + b_lrow + ks * 32);
                #pragma unroll
                for (int np = 0; np < 4; ++np)
                    if (np * 16 <= kmax_rel) {
                        mma_f16(s[2*np][0], s[2*np][1], s[2*np][2], s[2*np][3],
                                qf[ks][0], qf[ks][1], qf[ks][2], qf[ks][3],
                                b[np][0], b[np][1]);
                        mma_f16(s[2*np+1][0], s[2*np+1][1], s[2*np+1][2], s[2*np+1][3],
                                qf[ks][0], qf[ks][1], qf[ks][2], qf[ks][3],
                                b[np][2], b[np][3]);
                    }
            }

            // ---- causal mask (also covers skipped blocks: s=0 -> -inf) ----
            if (k0 + 63 > q0 + wr) {
                int r0l = q0 + wr + g, r1l = r0l + 8;
                #pragma unroll
                for (int nt = 0; nt < 8; ++nt) {
                    int c = k0 + nt * 8 + 2 * t;
                    if (c > r0l)     s[nt][0] = -CUDART_INF_F;
                    if (c + 1 > r0l) s[nt][1] = -CUDART_INF_F;
                    if (c > r1l)     s[nt][2] = -CUDART_INF_F;
                    if (c + 1 > r1l) s[nt][3] = -CUDART_INF_F;
                }
            }

            // ---- running max (row quads; only active blocks) ----
            float rm0 = s[0][0], rm1 = s[0][2];
            #pragma unroll
            for (int nt = 0; nt < 8; ++nt)
                if (nt * 8 <= kmax_rel) {
                    rm0 = fmaxf(rm0, fmaxf(s[nt][0], s[nt][1]));
                    rm1 = fmaxf(rm1, fmaxf(s[nt][2], s[nt][3]));
                }
            rm0 = fmaxf(rm0, __shfl_xor_sync(0xffffffffu, rm0, 1));
            rm0 = fmaxf(rm0, __shfl_xor_sync(0xffffffffu, rm0, 2));
            rm1 = fmaxf(rm1, __shfl_xor_sync(0xffffffffu, rm1, 1));
            rm1 = fmaxf(rm1, __shfl_xor_sync(0xffffffffu, rm1, 2));

            float mn0 = fmaxf(m0, rm0), mn1 = fmaxf(m1, rm1);

            // ---- ballot-gated rescale ----
            unsigned upd = __ballot_sync(0xffffffffu, (mn0 > m0) || (mn1 > m1));
            if (upd) {
                float corr0 = ex2f(m0 - mn0), corr1 = ex2f(m1 - mn1);
                #pragma unroll
                for (int nt = 0; nt < 8; ++nt) {
                    o[nt][0] *= corr0; o[nt][1] *= corr0;
                    o[nt][2] *= corr1; o[nt][3] *= corr1;
                }
                l0 *= corr0; l1 *= corr1;
                m0 = mn0; m1 = mn1;
            }

            // ---- P = 2^(s-m), packed fp16x2; row sums via HADD2 + fp32 accum ----
            uint32_t pa[4][4];
            #pragma unroll
            for (int ks = 0; ks < 4; ++ks)
                if (ks * 16 <= kmax_rel) {
                    pa[ks][0] = h2ex2(s[2*ks][0]   - m0, s[2*ks][1]   - m0);
                    pa[ks][1] = h2ex2(s[2*ks][2]   - m1, s[2*ks][3]   - m1);
                    pa[ks][2] = h2ex2(s[2*ks+1][0] - m0, s[2*ks+1][1] - m0);
                    pa[ks][3] = h2ex2(s[2*ks+1][2] - m1, s[2*ks+1][3] - m1);
                    // pair-add in fp16 (2 terms, exact-ish), then fp32 accumulate
                    __half2 h0 = __hadd2(*(__half2*)&pa[ks][0], *(__half2*)&pa[ks][2]);
                    __half2 h1 = __hadd2(*(__half2*)&pa[ks][1], *(__half2*)&pa[ks][3]);
                    float2 f0 = __half22float2(h0);
                    float2 f1 = __half22float2(h1);
                    l0 += f0.x + f0.y;
                    l1 += f1.x + f1.y;
                }

            // ---- O += P @ V (V via ldmatrix.trans); skip masked ks blocks ----
            #pragma unroll
            for (int ks = 0; ks < 4; ++ks)
                if (ks * 16 <= kmax_rel) {
                    uint32_t b[4][4];
                    #pragma unroll
                    for (int np = 0; np < 4; ++np)
                        LDSM_X4_T(b[np][0], b[np][1], b[np][2], b[np][3],
                                  Vs + (ks * 16) * FROWB + v_lrow + np * 32);
                    #pragma unroll
                    for (int np = 0; np < 4; ++np) {
                        mma_f16(o[2*np][0], o[2*np][1], o[2*np][2], o[2*np][3],
                                pa[ks][0], pa[ks][1], pa[ks][2], pa[ks][3],
                                b[np][0], b[np][1]);
                        mma_f16(o[2*np+1][0], o[2*np+1][1], o[2*np+1][2], o[2*np+1][3],
                                pa[ks][0], pa[ks][1], pa[ks][2], pa[ks][3],
                                b[np][2], b[np][3]);
                    }
                }
        }
    }

    // ---- final row-sum reduction over the quad (lanes sharing g) ----
    l0 += __shfl_xor_sync(0xffffffffu, l0, 1);
    l0 += __shfl_xor_sync(0xffffffffu, l0, 2);
    l1 += __shfl_xor_sync(0xffffffffu, l1, 1);
    l1 += __shfl_xor_sync(0xffffffffu, l1, 2);

    // ---- epilogue: normalize, store fp16 [b, s, h*dk] ----
    const int b = bh >> 4;
    const int h = bh & 15;
    const float inv0 = 1.0f / l0, inv1 = 1.0f / l1;
    const int r0g = q0 + wr + g, r1g = r0g + 8;
    #pragma unroll
    for (int nt = 0; nt < 8; ++nt) {
        int col = nt * 8 + 2 * t;
        *(__half2*)&Og[((size_t)(b * SS + r0g)) * DD + h * 64 + col] =
            __float22half2_rn(make_float2(o[nt][0] * inv0, o[nt][1] * inv0));
        *(__half2*)&Og[((size_t)(b * SS + r1g)) * DD + h * 64 + col] =
            __float22half2_rn(make_float2(o[nt][2] * inv1, o[nt][3] * inv1));
    }
}

// ---------------------------------------------------------------------------

extern "C" void kernel_launch(void* const* d_in, const int* in_sizes, int n_in,
                              void* d_out, int out_size)
{
    const float* x  = (const float*)d_in[0];
    const float* Wq = (const float*)d_in[1];
    const float* bq = (const float*)d_in[2];
    const float* Wk = (const float*)d_in[3];
    const float* bk = (const float*)d_in[4];
    const float* Wv = (const float*)d_in[5];
    const float* bv = (const float*)d_in[6];
    const float* Wo = (const float*)d_in[7];
    const float* bo = (const float*)d_in[8];
    const int*   pos = (const int*)d_in[9];
    float* out = (float*)d_out;

    __half *xh, *wh, *qh, *kh, *vh, *ah;
    float2* ropep;
    cudaGetSymbolAddress((void**)&xh, g_xh);
    cudaGetSymbolAddress((void**)&wh, g_wh);
    cudaGetSymbolAddress((void**)&qh, g_qh);
    cudaGetSymbolAddress((void**)&kh, g_kh);
    cudaGetSymbolAddress((void**)&vh, g_vh);
    cudaGetSymbolAddress((void**)&ah, g_ah);
    cudaGetSymbolAddress((void**)&ropep, g_rope);
    __half* who = wh + 3 * (size_t)DD * DD;

    prepass_kernel<<<NPRE / 256, 256>>>(
        (const float4*)x, (const float4*)Wq, (const float4*)Wk,
        (const float4*)Wv, (const float4*)Wo, xh, wh, pos, ropep);

    cudaFuncSetAttribute(gemm_h_kernel,
                         cudaFuncAttributeMaxDynamicSharedMemorySize, GEMM_SMEM);

    // fused QKV projection: W = [Wq|Wk|Wv] (3072 x 1024)
    gemm_h_kernel<<<dim3(3 * DD / 128, MM / 128), 256, GEMM_SMEM>>>(
        xh, wh, bq, bk, bv, ropep, qh, kh, vh, nullptr, 1);

    cudaFuncSetAttribute(flash_h_kernel,
                         cudaFuncAttributeMaxDynamicSharedMemorySize, FLASH_SMEM);
    flash_h_kernel<<<dim3(SS / 128, BB * HH), 256, FLASH_SMEM>>>(qh, kh, vh, ah);

    // output projection (float output)
    gemm_h_kernel<<<dim3(DD / 128, MM / 128), 256, GEMM_SMEM>>>(
        ah, who, bo, bo, bo, ropep, nullptr, nullptr, nullptr, out, 0);
}

// round 16
// speedup vs baseline: 1.1151x; 1.1151x over previous
#include <cuda_runtime.h>
#include <cuda_fp16.h>
#include <math_constants.h>
#include <cstdint>

// Problem constants (fixed by setup_inputs)
#define BB 2
#define SS 2048
#define HH 16
#define DKK 64
#define DD 1024
#define MM (BB*SS)   // 4096

// Scratch (allocation-free rule: __device__ globals)
__device__ __half g_xh[(size_t)MM * DD];         // fp16 x
__device__ __half g_wh[4 * (size_t)DD * DD];     // fp16 Wq,Wk,Wv,Wo (contiguous)
__device__ __half g_qh[(size_t)MM * DD];         // Q (pre-scaled by log2e/8, RoPE'd)
__device__ __half g_kh[(size_t)MM * DD];
__device__ __half g_vh[(size_t)MM * DD];
__device__ __half g_ah[(size_t)MM * DD];         // attention output
__device__ float2 g_rope[(size_t)MM * 32];       // (cos, sin) per (row, freq)

__device__ __forceinline__ void mma_f16(
    float& d0, float& d1, float& d2, float& d3,
    uint32_t a0, uint32_t a1, uint32_t a2, uint32_t a3,
    uint32_t b0, uint32_t b1)
{
    asm volatile(
        "mma.sync.aligned.m16n8k16.row.col.f32.f16.f16.f32 "
        "{%0,%1,%2,%3}, {%4,%5,%6,%7}, {%8,%9}, {%0,%1,%2,%3};\n"
        : "+f"(d0), "+f"(d1), "+f"(d2), "+f"(d3)
        : "r"(a0), "r"(a1), "r"(a2), "r"(a3), "r"(b0), "r"(b1));
}

#define LDSM_X4(r0,r1,r2,r3,addr) \
    asm volatile("ldmatrix.sync.aligned.m8n8.x4.shared.b16 {%0,%1,%2,%3}, [%4];" \
        : "=r"(r0), "=r"(r1), "=r"(r2), "=r"(r3) : "r"(addr))

#define LDSM_X4_T(r0,r1,r2,r3,addr) \
    asm volatile("ldmatrix.sync.aligned.m8n8.x4.trans.shared.b16 {%0,%1,%2,%3}, [%4];" \
        : "=r"(r0), "=r"(r1), "=r"(r2), "=r"(r3) : "r"(addr))

__device__ __forceinline__ void cp_async16(uint32_t dst, const void* src) {
    asm volatile("cp.async.cg.shared.global [%0], [%1], 16;\n" :: "r"(dst), "l"(src));
}

__device__ __forceinline__ uint32_t pack_h2(float lo, float hi) {
    __half2 h = __float22half2_rn(make_float2(lo, hi));
    return *(uint32_t*)&h;
}

__device__ __forceinline__ float ex2f(float x) {
    float y;
    asm("ex2.approx.f32 %0, %1;" : "=f"(y) : "f"(x));
    return y;
}

// pack (a,b) to half2 then 2^x elementwise with ONE MUFU op
__device__ __forceinline__ uint32_t h2ex2(float a, float b) {
    __half2 h = __float22half2_rn(make_float2(a, b));
    uint32_t u = *(uint32_t*)&h;
    asm("ex2.approx.f16x2 %0, %0;" : "+r"(u));
    return u;
}

// ---------------------------------------------------------------------------
// Fused prepass: fp16 conversion of x + 4 weights, AND RoPE table build.
// ---------------------------------------------------------------------------
#define NX8 (MM * DD / 8)        // 524288
#define NW8 (DD * DD / 8)        // 131072
#define NCVT (NX8 + 4 * NW8)     // 1048576
#define NPRE (NCVT + MM * 32)    // + rope units = 1179648

__global__ __launch_bounds__(256) void prepass_kernel(
    const float4* __restrict__ x,
    const float4* __restrict__ wq, const float4* __restrict__ wk,
    const float4* __restrict__ wv, const float4* __restrict__ wo,
    __half* __restrict__ xh, __half* __restrict__ wh,
    const int* __restrict__ pos, float2* __restrict__ rope)
{
    int i = blockIdx.x * 256 + threadIdx.x;
    if (i < NCVT) {
        const float4* src;
        __half* dst;
        int off;
        if (i < NX8) { src = x; dst = xh; off = i; }
        else {
            int j = i - NX8;
            int w = j / NW8;
            off = j - w * NW8;
            src = (w == 0) ? wq : (w == 1) ? wk : (w == 2) ? wv : wo;
            dst = wh + (size_t)w * (DD * DD);
        }
        float4 f0 = src[2 * off];
        float4 f1 = src[2 * off + 1];
        uint32_t h[4];
        h[0] = pack_h2(f0.x, f0.y);
        h[1] = pack_h2(f0.z, f0.w);
        h[2] = pack_h2(f1.x, f1.y);
        h[3] = pack_h2(f1.z, f1.w);
        *(uint4*)&dst[(size_t)off * 8] = make_uint4(h[0], h[1], h[2], h[3]);
    } else {
        int j = i - NCVT;                     // 0 .. MM*32-1
        int m = j >> 5, f = j & 31;
        const float KF = 0.14391157f;         // ln(10000)/64
        float invf = expf(-2.0f * (float)f * KF);
        float a = (float)pos[m] * invf;
        float sn, cs;
        sincosf(a, &sn, &cs);
        rope[j] = make_float2(cs, sn);
    }
}

// ---------------------------------------------------------------------------
// fp16 mma GEMM: C[M,N] = A[M,K] @ W[N,K]^T + bias (f32 accumulate).
// R12/R14 champion config: CTA tile 128x128, 8 warps of 64x32 (2Mx4N),
// 2 CTAs/SM. 4-stage cp.async ring, pair-loaded chunks, 1 sync / 2 chunks.
// ---------------------------------------------------------------------------
#define GROWB 80                    // bytes per smem row (40 halves)
#define G_A_BYTES (128 * GROWB)     // 10240
#define GSTG_B (2 * G_A_BYTES)      // 20480 per stage (A+B)
#define GNSTG 4
#define GEMM_SMEM (GNSTG * GSTG_B)  // 81920
#define GNC (DD / 32)               // 32 chunks (even)

__global__ __launch_bounds__(256, 2) void gemm_h_kernel(
    const __half* __restrict__ A, const __half* __restrict__ W,
    const float* __restrict__ bQ, const float* __restrict__ bK,
    const float* __restrict__ bV,
    const float2* __restrict__ rope,
    __half* __restrict__ oQ, __half* __restrict__ oK, __half* __restrict__ oV,
    float* __restrict__ outF, int mode)
{
    extern __shared__ char smc[];
    const uint32_t smem_u = (uint32_t)__cvta_generic_to_shared(smc);

    const int tid = threadIdx.x;
    const int lane = tid & 31;
    const int wid = tid >> 5;                 // 0..7
    const int g = lane >> 2;
    const int t = lane & 3;
    const int wm0 = (wid >> 2) * 64;          // 2 M groups
    const int wn0 = (wid & 3) * 32;           // 4 N groups
    const int m0 = blockIdx.y * 128;
    const int n0 = blockIdx.x * 128;

    // loader: chunk = 128 rows x 4 segs(16B) per matrix; 2 A + 2 B per thread
    const int seg = tid & 3;
    const int rbase = tid >> 2;               // 0..63; rows rbase + 64j
    const __half* aoff = A + (size_t)(m0 + rbase) * DD + seg * 8;
    const __half* boff = W + (size_t)(n0 + rbase) * DD + seg * 8;
    const uint32_t sdst = (uint32_t)(rbase * GROWB + seg * 16);

    float d[4][4][4];
    #pragma unroll
    for (int mt = 0; mt < 4; ++mt)
        #pragma unroll
        for (int nt = 0; nt < 4; ++nt)
            #pragma unroll
            for (int e = 0; e < 4; ++e) d[mt][nt][e] = 0.f;

    // prologue: chunks 0,1 as ONE group
    #pragma unroll
    for (int p = 0; p < 2; ++p) {
        uint32_t sb = smem_u + p * GSTG_B + sdst;
        #pragma unroll
        for (int j = 0; j < 2; ++j) {
            cp_async16(sb + j * (64 * GROWB), aoff + (size_t)j * 64 * DD + p * 32);
            cp_async16(sb + G_A_BYTES + j * (64 * GROWB), boff + (size_t)j * 64 * DD + p * 32);
        }
    }
    asm volatile("cp.async.commit_group;" ::: "memory");

    const uint32_t a_lrow = (uint32_t)((lane & 15) * GROWB + ((lane >> 4) << 4));
    const uint32_t b_lrow = (uint32_t)(((lane & 7) + ((lane >> 4) << 3)) * GROWB
                                       + (((lane >> 3) & 1) << 4));

    for (int kc = 0; kc < GNC; ++kc) {
        if ((kc & 1) == 0) {
            asm volatile("cp.async.wait_group 0;" ::: "memory");
            __syncthreads();
            if (kc + 2 < GNC) {
                #pragma unroll
                for (int p = 0; p < 2; ++p) {
                    const int c = kc + 2 + p;
                    uint32_t sb = smem_u + (c & 3) * GSTG_B + sdst;
                    const int ko = c * 32;
                    #pragma unroll
                    for (int j = 0; j < 2; ++j) {
                        cp_async16(sb + j * (64 * GROWB), aoff + (size_t)j * 64 * DD + ko);
                        cp_async16(sb + G_A_BYTES + j * (64 * GROWB), boff + (size_t)j * 64 * DD + ko);
                    }
                }
                asm volatile("cp.async.commit_group;" ::: "memory");
            }
        }

        const uint32_t Sa = smem_u + (kc & 3) * GSTG_B;
        const uint32_t Sb = Sa + G_A_BYTES;

        #pragma unroll
        for (int ks = 0; ks < 2; ++ks) {
            uint32_t a[4][4], b[2][4];
            #pragma unroll
            for (int mt = 0; mt < 4; ++mt)
                LDSM_X4(a[mt][0], a[mt][1], a[mt][2], a[mt][3],
                        Sa + (wm0 + mt * 16) * GROWB + a_lrow + ks * 32);
            #pragma unroll
            for (int np = 0; np < 2; ++np)
                LDSM_X4(b[np][0], b[np][1], b[np][2], b[np][3],
                        Sb + (wn0 + np * 16) * GROWB + b_lrow + ks * 32);
            #pragma unroll
            for (int mt = 0; mt < 4; ++mt)
                #pragma unroll
                for (int np = 0; np < 2; ++np) {
                    mma_f16(d[mt][2*np][0], d[mt][2*np][1], d[mt][2*np][2], d[mt][2*np][3],
                            a[mt][0], a[mt][1], a[mt][2], a[mt][3], b[np][0], b[np][1]);
                    mma_f16(d[mt][2*np+1][0], d[mt][2*np+1][1], d[mt][2*np+1][2], d[mt][2*np+1][3],
                            a[mt][0], a[mt][1], a[mt][2], a[mt][3], b[np][2], b[np][3]);
                }
        }
    }

    // ---- epilogue (warp tile 64x32) ----
    #pragma unroll
    for (int mt = 0; mt < 4; ++mt) {
        int r0 = m0 + wm0 + mt * 16 + g;
        int r1 = r0 + 8;
        const float2* rp0 = rope + (size_t)r0 * 32;
        const float2* rp1 = rope + (size_t)r1 * 32;
        #pragma unroll
        for (int nt = 0; nt < 4; ++nt) {
            int c = n0 + wn0 + nt * 8 + 2 * t;
            if (mode == 0) {
                float bv0 = __ldg(bQ + c), bv1 = __ldg(bQ + c + 1);
                *(float2*)&outF[(size_t)r0 * DD + c] =
                    make_float2(d[mt][nt][0] + bv0, d[mt][nt][1] + bv1);
                *(float2*)&outF[(size_t)r1 * DD + c] =
                    make_float2(d[mt][nt][2] + bv0, d[mt][nt][3] + bv1);
            } else {
                const int which = c >> 10;        // 0=Q 1=K 2=V
                const int cc = c & 1023;
                const int h = cc >> 6, cl = cc & 63;
                const float* bp = (which == 0) ? bQ : (which == 1) ? bK : bV;
                __half* outp = (which == 0) ? oQ : (which == 1) ? oK : oV;
                float bv0 = __ldg(bp + cc), bv1 = __ldg(bp + cc + 1);
                float v00 = d[mt][nt][0] + bv0, v01 = d[mt][nt][1] + bv1;
                float v10 = d[mt][nt][2] + bv0, v11 = d[mt][nt][3] + bv1;
                if (which < 2) {                  // RoPE on Q,K
                    float2 cs0 = rp0[cl >> 1], cs1 = rp1[cl >> 1];
                    float e, od;
                    e  = v00 * cs0.x - v01 * cs0.y;
                    od = v00 * cs0.y + v01 * cs0.x;  v00 = e; v01 = od;
                    e  = v10 * cs1.x - v11 * cs1.y;
                    od = v10 * cs1.y + v11 * cs1.x;  v10 = e; v11 = od;
                }
                // Q pre-scale: (1/sqrt(dk)) * log2(e) -> flash softmax in log2 domain
                float sc = (which == 0) ? 0.18033688f : 1.0f;
                int b0i = r0 >> 11, s0 = r0 & (SS - 1);
                int b1i = r1 >> 11, s1 = r1 & (SS - 1);
                size_t o0 = (((size_t)(b0i * HH + h) * SS + s0) * DKK) + cl;
                size_t o1 = (((size_t)(b1i * HH + h) * SS + s1) * DKK) + cl;
                *(__half2*)&outp[o0] = __float22half2_rn(make_float2(v00 * sc, v01 * sc));
                *(__half2*)&outp[o1] = __float22half2_rn(make_float2(v10 * sc, v11 * sc));
            }
        }
    }
}

// ---------------------------------------------------------------------------
// fp16 tensor-core flash attention (log2-domain softmax, causal).
// R14 internals, plus DIAGONAL Q-TILE PAIRING: each CTA processes q-tiles
// (15 - bx) then (bx) -> uniform cost 34 tile-units per CTA, 256 CTAs =
// one perfectly balanced wave (2 CTAs/SM, 296 slots).
// Br=128 (8 warps x 16 rows), Bc=64, 4-stage pair-loaded KV ring.
// ---------------------------------------------------------------------------
#define FROWB 144                       // bytes per smem row (72 halves)
#define FTILE_B (64 * FROWB)            // 9216 B per tensor per stage
#define FSTG_B (2 * FTILE_B)            // 18432 B per stage (K+V)
#define FNSTG 4
#define FLASH_SMEM (FNSTG * FSTG_B)     // 73728 B
#define H2_ONES 0x3C003C00u             // (1.0h, 1.0h)
#define NQT (SS / 128)                  // 16 q-tiles per (b,h)

__global__ __launch_bounds__(256, 2) void flash_h_kernel(
    const __half* __restrict__ Qg, const __half* __restrict__ Kg,
    const __half* __restrict__ Vg, __half* __restrict__ Og)
{
    extern __shared__ char smc[];
    __half* smh = (__half*)smc;
    const uint32_t smem_u = (uint32_t)__cvta_generic_to_shared(smc);

    const int bh = blockIdx.y;
    const __half* Qb = Qg + (size_t)bh * SS * DKK;
    const __half* Kb = Kg + (size_t)bh * SS * DKK;
    const __half* Vb = Vg + (size_t)bh * SS * DKK;

    const int tid = threadIdx.x;
    const int lane = tid & 31;
    const int wid = tid >> 5;
    const int g = lane >> 2;
    const int t = lane & 3;
    const int wr = wid * 16;          // warp row base (0..112)

    const uint32_t a_lrow = (uint32_t)((lane & 15) * FROWB + ((lane >> 4) << 4));
    const uint32_t b_lrow = (uint32_t)(((lane & 7) + ((lane >> 4) << 3)) * FROWB
                                       + (((lane >> 3) & 1) << 4));
    const uint32_t v_lrow = (uint32_t)(((lane & 7) + (((lane >> 3) & 1) << 3)) * FROWB
                                       + ((lane >> 4) << 4));

    // KV loader decomposition (q-tile independent)
    const int fr = tid >> 3;
    const int fsg = tid & 7;
    const __half* ksrc = Kb + (size_t)fr * DKK + fsg * 8;
    const __half* vsrc = Vb + (size_t)fr * DKK + fsg * 8;
    const uint32_t kdst = smem_u + (uint32_t)(fr * FROWB + fsg * 16);
    const uint32_t vdst = kdst + FTILE_B;

    #pragma unroll
    for (int sub = 0; sub < 2; ++sub) {
        // big tile first, then the complementary small tile: cost sums to 34
        const int qi = sub == 0 ? (NQT - 1 - (int)blockIdx.x) : (int)blockIdx.x;
        const int q0 = qi * 128;

        // ---- stage Q tile (128 x 64 halves, row stride 72) into stage-0 area ----
        #pragma unroll
        for (int j = 0; j < 4; ++j) {
            int u = tid + j * 256;        // 0..1023
            int row = u >> 3;
            int sg = u & 7;
            uint4 v = *(const uint4*)&Qb[(size_t)(q0 + row) * DKK + sg * 8];
            *(uint4*)&smh[row * 72 + sg * 8] = v;
        }
        __syncthreads();

        uint32_t qf[4][4];
        #pragma unroll
        for (int ks = 0; ks < 4; ++ks)
            LDSM_X4(qf[ks][0], qf[ks][1], qf[ks][2], qf[ks][3],
                    smem_u + wr * FROWB + a_lrow + ks * 32);
        __syncthreads();   // Q reads done before KV tile 0 overwrites stage 0

        const int rmax = q0 + wr + 15;
        const int ktend = 2 * qi + 2;     // even

        // prologue: KV tiles 0,1 as ONE group
        #pragma unroll
        for (int p = 0; p < 2; ++p) {
            uint32_t so = (uint32_t)(p * FSTG_B);
            const size_t go = (size_t)p * 64 * DKK;
            #pragma unroll
            for (int j = 0; j < 2; ++j) {
                cp_async16(kdst + so + j * (32 * FROWB), ksrc + go + (size_t)j * 32 * DKK);
                cp_async16(vdst + so + j * (32 * FROWB), vsrc + go + (size_t)j * 32 * DKK);
            }
        }
        asm volatile("cp.async.commit_group;" ::: "memory");

        float o[8][4];
        #pragma unroll
        for (int nt = 0; nt < 8; ++nt)
            #pragma unroll
            for (int e = 0; e < 4; ++e) o[nt][e] = 0.f;
        float ls[4] = {0.f, 0.f, 0.f, 0.f};   // row-sum accumulator (ones-mma)
        float m0 = -CUDART_INF_F, m1 = -CUDART_INF_F;

        for (int kt = 0; kt < ktend; ++kt) {
            const int k0 = kt * 64;

            if ((kt & 1) == 0) {
                asm volatile("cp.async.wait_group 0;" ::: "memory");
                __syncthreads();
                if (kt + 2 < ktend) {
                    #pragma unroll
                    for (int p = 0; p < 2; ++p) {
                        const int tt = kt + 2 + p;
                        uint32_t so = (uint32_t)((tt & 3) * FSTG_B);
                        const size_t go = (size_t)tt * 64 * DKK;
                        #pragma unroll
                        for (int j = 0; j < 2; ++j) {
                            cp_async16(kdst + so + j * (32 * FROWB), ksrc + go + (size_t)j * 32 * DKK);
                            cp_async16(vdst + so + j * (32 * FROWB), vsrc + go + (size_t)j * 32 * DKK);
                        }
                    }
                    asm volatile("cp.async.commit_group;" ::: "memory");
                }
            }

            if (k0 <= rmax) {
                const uint32_t Ks = smem_u + (kt & 3) * FSTG_B;
                const uint32_t Vs = Ks + FTILE_B;

                // ---- S = Q @ K^T (log2-domain scores) ----
                float s[8][4];
                #pragma unroll
                for (int nt = 0; nt < 8; ++nt)
                    #pragma unroll
                    for (int e = 0; e < 4; ++e) s[nt][e] = 0.f;

                #pragma unroll
                for (int ks = 0; ks < 4; ++ks) {
                    uint32_t b[4][4];
                    #pragma unroll
                    for (int np = 0; np < 4; ++np)
                        LDSM_X4(b[np][0], b[np][1], b[np][2], b[np][3],
                                Ks + (np * 16) * FROWB + b_lrow + ks * 32);
                    #pragma unroll
                    for (int np = 0; np < 4; ++np) {
                        mma_f16(s[2*np][0], s[2*np][1], s[2*np][2], s[2*np][3],
                                qf[ks][0], qf[ks][1], qf[ks][2], qf[ks][3],
                                b[np][0], b[np][1]);
                        mma_f16(s[2*np+1][0], s[2*np+1][1], s[2*np+1][2], s[2*np+1][3],
                                qf[ks][0], qf[ks][1], qf[ks][2], qf[ks][3],
                                b[np][2], b[np][3]);
                    }
                }

                // ---- causal mask ----
                if (k0 + 63 > q0 + wr) {
                    int r0l = q0 + wr + g, r1l = r0l + 8;
                    #pragma unroll
                    for (int nt = 0; nt < 8; ++nt) {
                        int c = k0 + nt * 8 + 2 * t;
                        if (c > r0l)     s[nt][0] = -CUDART_INF_F;
                        if (c + 1 > r0l) s[nt][1] = -CUDART_INF_F;
                        if (c > r1l)     s[nt][2] = -CUDART_INF_F;
                        if (c + 1 > r1l) s[nt][3] = -CUDART_INF_F;
                    }
                }

                // ---- running max (row quads) ----
                float rm0 = s[0][0], rm1 = s[0][2];
                #pragma unroll
                for (int nt = 0; nt < 8; ++nt) {
                    rm0 = fmaxf(rm0, fmaxf(s[nt][0], s[nt][1]));
                    rm1 = fmaxf(rm1, fmaxf(s[nt][2], s[nt][3]));
                }
                rm0 = fmaxf(rm0, __shfl_xor_sync(0xffffffffu, rm0, 1));
                rm0 = fmaxf(rm0, __shfl_xor_sync(0xffffffffu, rm0, 2));
                rm1 = fmaxf(rm1, __shfl_xor_sync(0xffffffffu, rm1, 1));
                rm1 = fmaxf(rm1, __shfl_xor_sync(0xffffffffu, rm1, 2));

                float mn0 = fmaxf(m0, rm0), mn1 = fmaxf(m1, rm1);

                // ---- ballot-gated rescale ----
                unsigned upd = __ballot_sync(0xffffffffu, (mn0 > m0) || (mn1 > m1));
                if (upd) {
                    float corr0 = ex2f(m0 - mn0), corr1 = ex2f(m1 - mn1);
                    #pragma unroll
                    for (int nt = 0; nt < 8; ++nt) {
                        o[nt][0] *= corr0; o[nt][1] *= corr0;
                        o[nt][2] *= corr1; o[nt][3] *= corr1;
                    }
                    ls[0] *= corr0; ls[1] *= corr0;
                    ls[2] *= corr1; ls[3] *= corr1;
                    m0 = mn0; m1 = mn1;
                }

                // ---- P = 2^(s-m), packed fp16x2 ----
                uint32_t pa[4][4];
                #pragma unroll
                for (int ks = 0; ks < 4; ++ks) {
                    pa[ks][0] = h2ex2(s[2*ks][0]   - m0, s[2*ks][1]   - m0);
                    pa[ks][1] = h2ex2(s[2*ks][2]   - m1, s[2*ks][3]   - m1);
                    pa[ks][2] = h2ex2(s[2*ks+1][0] - m0, s[2*ks+1][1] - m0);
                    pa[ks][3] = h2ex2(s[2*ks+1][2] - m1, s[2*ks+1][3] - m1);
                }

                // ---- row sums via ones-mma ----
                #pragma unroll
                for (int ks = 0; ks < 4; ++ks)
                    mma_f16(ls[0], ls[1], ls[2], ls[3],
                            pa[ks][0], pa[ks][1], pa[ks][2], pa[ks][3],
                            H2_ONES, H2_ONES);

                // ---- O += P @ V  (V via ldmatrix.trans) ----
                #pragma unroll
                for (int ks = 0; ks < 4; ++ks) {
                    uint32_t b[4][4];
                    #pragma unroll
                    for (int np = 0; np < 4; ++np)
                        LDSM_X4_T(b[np][0], b[np][1], b[np][2], b[np][3],
                                  Vs + (ks * 16) * FROWB + v_lrow + np * 32);
                    #pragma unroll
                    for (int np = 0; np < 4; ++np) {
                        mma_f16(o[2*np][0], o[2*np][1], o[2*np][2], o[2*np][3],
                                pa[ks][0], pa[ks][1], pa[ks][2], pa[ks][3],
                                b[np][0], b[np][1]);
                        mma_f16(o[2*np+1][0], o[2*np+1][1], o[2*np+1][2], o[2*np+1][3],
                                pa[ks][0], pa[ks][1], pa[ks][2], pa[ks][3],
                                b[np][2], b[np][3]);
                    }
                }
            }
        }

        // ---- epilogue: normalize, store fp16 [b, s, h*dk] ----
        const int b = bh >> 4;
        const int h = bh & 15;
        const float inv0 = 1.0f / ls[0], inv1 = 1.0f / ls[2];
        const int r0g = q0 + wr + g, r1g = r0g + 8;
        #pragma unroll
        for (int nt = 0; nt < 8; ++nt) {
            int col = nt * 8 + 2 * t;
            *(__half2*)&Og[((size_t)(b * SS + r0g)) * DD + h * 64 + col] =
                __float22half2_rn(make_float2(o[nt][0] * inv0, o[nt][1] * inv0));
            *(__half2*)&Og[((size_t)(b * SS + r1g)) * DD + h * 64 + col] =
                __float22half2_rn(make_float2(o[nt][2] * inv1, o[nt][3] * inv1));
        }

        // all KV-ring reads done before next sub overwrites smem with Q
        __syncthreads();
    }
}

// ---------------------------------------------------------------------------

extern "C" void kernel_launch(void* const* d_in, const int* in_sizes, int n_in,
                              void* d_out, int out_size)
{
    const float* x  = (const float*)d_in[0];
    const float* Wq = (const float*)d_in[1];
    const float* bq = (const float*)d_in[2];
    const float* Wk = (const float*)d_in[3];
    const float* bk = (const float*)d_in[4];
    const float* Wv = (const float*)d_in[5];
    const float* bv = (const float*)d_in[6];
    const float* Wo = (const float*)d_in[7];
    const float* bo = (const float*)d_in[8];
    const int*   pos = (const int*)d_in[9];
    float* out = (float*)d_out;

    __half *xh, *wh, *qh, *kh, *vh, *ah;
    float2* ropep;
    cudaGetSymbolAddress((void**)&xh, g_xh);
    cudaGetSymbolAddress((void**)&wh, g_wh);
    cudaGetSymbolAddress((void**)&qh, g_qh);
    cudaGetSymbolAddress((void**)&kh, g_kh);
    cudaGetSymbolAddress((void**)&vh, g_vh);
    cudaGetSymbolAddress((void**)&ah, g_ah);
    cudaGetSymbolAddress((void**)&ropep, g_rope);
    __half* who = wh + 3 * (size_t)DD * DD;

    prepass_kernel<<<NPRE / 256, 256>>>(
        (const float4*)x, (const float4*)Wq, (const float4*)Wk,
        (const float4*)Wv, (const float4*)Wo, xh, wh, pos, ropep);

    cudaFuncSetAttribute(gemm_h_kernel,
                         cudaFuncAttributeMaxDynamicSharedMemorySize, GEMM_SMEM);

    // fused QKV projection: W = [Wq|Wk|Wv] (3072 x 1024)
    gemm_h_kernel<<<dim3(3 * DD / 128, MM / 128), 256, GEMM_SMEM>>>(
        xh, wh, bq, bk, bv, ropep, qh, kh, vh, nullptr, 1);

    cudaFuncSetAttribute(flash_h_kernel,
                         cudaFuncAttributeMaxDynamicSharedMemorySize, FLASH_SMEM);
    flash_h_kernel<<<dim3(NQT / 2, BB * HH), 256, FLASH_SMEM>>>(qh, kh, vh, ah);

    // output projection (float output)
    gemm_h_kernel<<<dim3(DD / 128, MM / 128), 256, GEMM_SMEM>>>(
        ah, who, bo, bo, bo, ropep, nullptr, nullptr, nullptr, out, 0);
}